// round 15
// baseline (speedup 1.0000x reference)
#include <cuda_runtime.h>
#include <cuda_fp16.h>
#include <cstdint>

// ---------------------------------------------------------------------------
// Problem constants
// ---------------------------------------------------------------------------
#define B_SZ   8
#define T_SZ   2048
#define C_SZ   1024
#define H_SZ   16
#define DH     64
#define BH     (B_SZ * H_SZ)     // 128
#define C3     (3 * C_SZ)        // 3072
#define M_ROWS (B_SZ * T_SZ)     // 16384
#define MW     64
#define PP     8
#define NLEV   4

__device__ __constant__ size_t POOL_OFF[4] = {
    0,
    (size_t)BH * 256 * DH,
    (size_t)BH * 256 * DH + (size_t)BH * 128 * DH,
    (size_t)BH * 256 * DH + (size_t)BH * 128 * DH + (size_t)BH * 64 * DH
};
#define POOL_TOTAL ((size_t)BH * (256 + 128 + 64 + 32) * DH)

// ---------------------------------------------------------------------------
// Scratch (static device allocations)
// ---------------------------------------------------------------------------
__device__ __half g_qkv_h [(size_t)M_ROWS * C3];     // 100 MB fp16 qkv
__device__ __half g_x_h   [(size_t)M_ROWS * C_SZ];
__device__ __half g_attn_h[(size_t)M_ROWS * C_SZ];
__device__ __half g_kpool [POOL_TOTAL];
__device__ __half g_vpool [POOL_TOTAL];
__device__ __half g_wt_attn[(size_t)C3 * C_SZ];
__device__ __half g_wt_proj[(size_t)C_SZ * C_SZ];

// ===========================================================================
// PTX helpers
// ===========================================================================
__device__ __forceinline__ uint32_t smem_u32(const void* p) {
    uint32_t a;
    asm("{ .reg .u64 t; cvta.to.shared.u64 t, %1; cvt.u32.u64 %0, t; }" : "=r"(a) : "l"(p));
    return a;
}
__device__ __forceinline__ void cp_async16(uint32_t saddr, const void* g) {
    asm volatile("cp.async.cg.shared.global [%0], [%1], 16;" :: "r"(saddr), "l"(g));
}
__device__ __forceinline__ void cp_commit() {
    asm volatile("cp.async.commit_group;" ::: "memory");
}
template <int N>
__device__ __forceinline__ void cp_wait() {
    asm volatile("cp.async.wait_group %0;" :: "n"(N) : "memory");
}
__device__ __forceinline__ void ldm_x4(uint32_t& r0, uint32_t& r1, uint32_t& r2,
                                       uint32_t& r3, uint32_t addr) {
    asm volatile("ldmatrix.sync.aligned.m8n8.x4.shared.b16 {%0,%1,%2,%3}, [%4];"
                 : "=r"(r0), "=r"(r1), "=r"(r2), "=r"(r3) : "r"(addr));
}
__device__ __forceinline__ void ldm_x4t(uint32_t& r0, uint32_t& r1, uint32_t& r2,
                                        uint32_t& r3, uint32_t addr) {
    asm volatile("ldmatrix.sync.aligned.m8n8.x4.trans.shared.b16 {%0,%1,%2,%3}, [%4];"
                 : "=r"(r0), "=r"(r1), "=r"(r2), "=r"(r3) : "r"(addr));
}
__device__ __forceinline__ void mma16816(float* d, const uint32_t* a, const uint32_t* b) {
    asm volatile(
        "mma.sync.aligned.m16n8k16.row.col.f32.f16.f16.f32 "
        "{%0,%1,%2,%3}, {%4,%5,%6,%7}, {%8,%9}, {%0,%1,%2,%3};"
        : "+f"(d[0]), "+f"(d[1]), "+f"(d[2]), "+f"(d[3])
        : "r"(a[0]), "r"(a[1]), "r"(a[2]), "r"(a[3]), "r"(b[0]), "r"(b[1]));
}

// ===========================================================================
// Prep kernels
// ===========================================================================
__global__ void convert_f2h(const float* __restrict__ in, __half* __restrict__ out,
                            size_t n)
{
    const size_t i = ((size_t)blockIdx.x * blockDim.x + threadIdx.x) * 4;
    if (i < n) {
        float4 v = *(const float4*)(in + i);
        *(__half2*)(out + i)     = __floats2half2_rn(v.x, v.y);
        *(__half2*)(out + i + 2) = __floats2half2_rn(v.z, v.w);
    }
}

__global__ void transpose_kh(const float* __restrict__ W, __half* __restrict__ Wt,
                             int K, int N)
{
    __shared__ float t[32][33];
    const int x = blockIdx.x * 32 + threadIdx.x;
    const int y = blockIdx.y * 32 + threadIdx.y;
#pragma unroll
    for (int j = 0; j < 32; j += 8)
        t[threadIdx.y + j][threadIdx.x] = W[(size_t)(y + j) * N + x];
    __syncthreads();
    const int xo = blockIdx.y * 32 + threadIdx.x;
    const int yo = blockIdx.x * 32 + threadIdx.y;
#pragma unroll
    for (int j = 0; j < 32; j += 8)
        Wt[(size_t)(yo + j) * K + xo] = __float2half(t[threadIdx.x][threadIdx.y + j]);
}

// ===========================================================================
// HGEMM: 128x128 tile, K-chunk 64/stage, 3 stages, warp 64x32.
// Verified plateau config (~315-337us, 58% tensor).
// ===========================================================================
#define HBM_T 128
#define HBN_T 128
#define HBK_T 64
#define HSTAGES 3
#define HPITCH 144
#define HSTAGE_BYTES (2 * 128 * HPITCH)                 // 36864
#define HGEMM_SMEM (HSTAGES * HSTAGE_BYTES)             // 110592

template <int HALF_OUT>
__global__ __launch_bounds__(256, 2)
void hgemm_bias(const __half* __restrict__ Ah, const __half* __restrict__ Bh,
                const float* __restrict__ bias, void* __restrict__ Cout,
                int M, int N, int K)
{
    extern __shared__ char smem[];
    const uint32_t sb = smem_u32(smem);
    const int tid  = threadIdx.x;
    const int wid  = tid >> 5;
    const int lane = tid & 31;

    const int row0 = blockIdx.y * HBM_T;
    const int col0 = blockIdx.x * HBN_T;
    const int m0   = (wid & 1) * 64;
    const int n0   = (wid >> 1) * 32;
    const int NT   = K / HBK_T;                          // 16

    const int mat = lane >> 3, li = lane & 7;
    const int rowA = (mat & 1) * 8 + li;
    const int kA   = (mat >> 1) * 8;
    const int rowB = (mat >> 1) * 8 + li;
    const int kB   = (mat & 1) * 8;

    float acc[4][4][4];
#pragma unroll
    for (int i = 0; i < 4; i++)
#pragma unroll
        for (int j = 0; j < 4; j++)
#pragma unroll
            for (int r = 0; r < 4; r++) acc[i][j][r] = 0.f;

    auto load_tile = [&](int t) {
        const uint32_t sA = sb + (t % HSTAGES) * HSTAGE_BYTES;
        const uint32_t sB = sA + 128 * HPITCH;
        const int k0 = t * HBK_T;
#pragma unroll
        for (int i = 0; i < 4; i++) {
            const int id = i * 256 + tid;
            const int r = id >> 3, c = id & 7;
            cp_async16(sA + r * HPITCH + c * 16, Ah + (size_t)(row0 + r) * K + k0 + c * 8);
        }
#pragma unroll
        for (int i = 0; i < 4; i++) {
            const int id = i * 256 + tid;
            const int r = id >> 3, c = id & 7;
            cp_async16(sB + r * HPITCH + c * 16, Bh + (size_t)(col0 + r) * K + k0 + c * 8);
        }
    };

    for (int t = 0; t < HSTAGES - 1; t++) { load_tile(t); cp_commit(); }

    for (int kt = 0; kt < NT; kt++) {
        cp_wait<HSTAGES - 2>();
        __syncthreads();
        const int pf = kt + HSTAGES - 1;
        if (pf < NT) load_tile(pf);
        cp_commit();

        const uint32_t sA = sb + (kt % HSTAGES) * HSTAGE_BYTES;
        const uint32_t sB = sA + 128 * HPITCH;
#pragma unroll
        for (int kc = 0; kc < 4; kc++) {
            uint32_t af[4][4], bf[2][4];
#pragma unroll
            for (int mt = 0; mt < 4; mt++)
                ldm_x4(af[mt][0], af[mt][1], af[mt][2], af[mt][3],
                       sA + (m0 + mt * 16 + rowA) * HPITCH + (kc * 16 + kA) * 2);
#pragma unroll
            for (int np = 0; np < 2; np++)
                ldm_x4(bf[np][0], bf[np][1], bf[np][2], bf[np][3],
                       sB + (n0 + np * 16 + rowB) * HPITCH + (kc * 16 + kB) * 2);
#pragma unroll
            for (int mt = 0; mt < 4; mt++)
#pragma unroll
                for (int nt = 0; nt < 4; nt++)
                    mma16816(acc[mt][nt], af[mt], &bf[nt >> 1][(nt & 1) * 2]);
        }
    }
    cp_wait<0>();

#pragma unroll
    for (int mt = 0; mt < 4; mt++) {
#pragma unroll
        for (int nt = 0; nt < 4; nt++) {
            const int r  = row0 + m0 + mt * 16 + (lane >> 2);
            const int cc = col0 + n0 + nt * 8 + (lane & 3) * 2;
            const float b0 = bias[cc], b1 = bias[cc + 1];
            if (HALF_OUT) {
                __half* C = (__half*)Cout;
                *(__half2*)(C + (size_t)r * N + cc) =
                    __floats2half2_rn(acc[mt][nt][0] + b0, acc[mt][nt][1] + b1);
                *(__half2*)(C + (size_t)(r + 8) * N + cc) =
                    __floats2half2_rn(acc[mt][nt][2] + b0, acc[mt][nt][3] + b1);
            } else {
                float* C = (float*)Cout;
                float2 v0 = { acc[mt][nt][0] + b0, acc[mt][nt][1] + b1 };
                float2 v1 = { acc[mt][nt][2] + b0, acc[mt][nt][3] + b1 };
                *(float2*)(C + (size_t)r * N + cc)       = v0;
                *(float2*)(C + (size_t)(r + 8) * N + cc) = v1;
            }
        }
    }
}

// ---------------------------------------------------------------------------
// Fused hierarchical pooling: one CTA per bh (128 CTAs, single wave).
// Level 0 reads raw K/V once; levels 1..3 reduce from smem.
// smem layout (halves): K levels at row offsets {0,256,384,448}, 480 rows;
// then V at the same offsets + 480 rows. Pitch 64 halves.
// ---------------------------------------------------------------------------
#define POOL_SMEM_BYTES (2 * 480 * 64 * 2)   // 122880
__device__ __constant__ int LV_ROW[4] = {0, 256, 384, 448};

__global__ void pool_all(const __half* __restrict__ qkv,
                         __half* __restrict__ kp, __half* __restrict__ vp)
{
    extern __shared__ __half sp[];
    __half* sk = sp;
    __half* sv = sp + 480 * 64;

    const int bh = blockIdx.x;
    const int b = bh >> 4, h = bh & 15;
    const size_t kb = (size_t)b * T_SZ * C3 + h * DH + C_SZ;
    const size_t vb = kb + C_SZ;
    const int tid = threadIdx.x;

    // ---- level 0: 256 rows, avg of 8 raw timesteps ----
    for (int idx = tid; idx < 256 * 32; idx += 256) {
        const int pi = idx >> 5;
        const int d2 = (idx & 31) * 2;
        float skx = 0.f, sky = 0.f, svx = 0.f, svy = 0.f;
        const int t0 = pi * 8;
#pragma unroll
        for (int i = 0; i < 8; i++) {
            float2 k2 = __half22float2(*(const __half2*)(qkv + kb + (size_t)(t0 + i) * C3 + d2));
            float2 v2 = __half22float2(*(const __half2*)(qkv + vb + (size_t)(t0 + i) * C3 + d2));
            skx += k2.x; sky += k2.y; svx += v2.x; svy += v2.y;
        }
        __half2 hk = __floats2half2_rn(skx * 0.125f, sky * 0.125f);
        __half2 hv = __floats2half2_rn(svx * 0.125f, svy * 0.125f);
        *(__half2*)(sk + pi * 64 + d2) = hk;
        *(__half2*)(sv + pi * 64 + d2) = hv;
        const size_t o = ((size_t)bh * 256 + pi) * DH + d2;
        *(__half2*)(kp + o) = hk;
        *(__half2*)(vp + o) = hv;
    }
    __syncthreads();

    // ---- levels 1..3: avg 2 rows of previous level (distinct smem regions) ----
#pragma unroll
    for (int l = 1; l <= 3; l++) {
        const int nl = 256 >> l;
        const int srow = LV_ROW[l - 1], drow = LV_ROW[l];
        const size_t gdst = POOL_OFF[l] + (size_t)bh * nl * DH;
        for (int idx = tid; idx < nl * 32; idx += 256) {
            const int pi = idx >> 5, d2 = (idx & 31) * 2;
            {
                float2 a = __half22float2(*(const __half2*)(sk + (srow + 2 * pi) * 64 + d2));
                float2 c = __half22float2(*(const __half2*)(sk + (srow + 2 * pi + 1) * 64 + d2));
                __half2 r = __floats2half2_rn(0.5f * (a.x + c.x), 0.5f * (a.y + c.y));
                *(__half2*)(sk + (drow + pi) * 64 + d2) = r;
                *(__half2*)(kp + gdst + (size_t)pi * DH + d2) = r;
            }
            {
                float2 a = __half22float2(*(const __half2*)(sv + (srow + 2 * pi) * 64 + d2));
                float2 c = __half22float2(*(const __half2*)(sv + (srow + 2 * pi + 1) * 64 + d2));
                __half2 r = __floats2half2_rn(0.5f * (a.x + c.x), 0.5f * (a.y + c.y));
                *(__half2*)(sv + (drow + pi) * 64 + d2) = r;
                *(__half2*)(vp + gdst + (size_t)pi * DH + d2) = r;
            }
        }
        __syncthreads();
    }
}

// ---------------------------------------------------------------------------
// Fused MLA attention — tensor cores (round-13/14 verified version).
// ---------------------------------------------------------------------------
#define AQH 0
#define AKH 9216
#define ASS 32256
#define AWH 74240
#define ATTN2_BYTES 95744
#define QP  72
#define KP  72
#define SP  164
#define WP  168

__global__ __launch_bounds__(256, 2)
void mla_attn(const __half* __restrict__ qkv,
              const __half* __restrict__ kpool,
              const __half* __restrict__ vpool,
              __half* __restrict__ o)
{
    extern __shared__ char smem[];
    const uint32_t sb = smem_u32(smem);
    float* sS = (float*)(smem + ASS);
    __half* sWh = (__half*)(smem + AWH);

    const int qb  = blockIdx.x;
    const int bh  = blockIdx.y;
    const int b   = bh >> 4, h = bh & 15;
    const int tid = threadIdx.x;
    const int wid = tid >> 5;
    const int lane = tid & 31;

    const size_t baseQ = (size_t)b * T_SZ * C3 + h * DH;
    const size_t baseK = baseQ + C_SZ;
    const size_t baseV = baseQ + 2 * C_SZ;

    const int mat = lane >> 3, li = lane & 7;
    const int rowA = (mat & 1) * 8 + li;
    const int kA   = (mat >> 1) * 8;
    const int rowB = (mat >> 1) * 8 + li;
    const int kB   = (mat & 1) * 8;

    // --- load Q (unscaled) via cp.async ---
    for (int i = tid; i < 64 * 8; i += 256) {
        const int r = i >> 3, c = (i & 7) * 8;
        cp_async16(sb + AQH + r * (QP * 2) + c * 2,
                   qkv + baseQ + (size_t)(qb * MW + r) * C3 + c);
    }
    // --- load K (fine 128 + coarse 32) via cp.async ---
    {
        const uint4 zero = {0u, 0u, 0u, 0u};
        for (int i = tid; i < 160 * 8; i += 256) {
            const int r = i >> 3, c = (i & 7) * 8;
            const uint32_t dst = sb + AKH + r * (KP * 2) + c * 2;
            if (r < 128) {
                const int t = qb * MW - MW + r;
                if (t >= 0) cp_async16(dst, qkv + baseK + (size_t)t * C3 + c);
                else        *(uint4*)(smem + AKH + r * (KP * 2) + c * 2) = zero;
            } else {
                const int rr = r - 128, l0 = rr >> 3, ix = rr & 7;
                const int cb = (qb >> l0) - 1;
                if (cb >= 0) {
                    const int nl = 256 >> l0;
                    cp_async16(dst, kpool + POOL_OFF[l0] +
                                    ((size_t)bh * nl + cb * PP + ix) * DH + c);
                } else {
                    *(uint4*)(smem + AKH + r * (KP * 2) + c * 2) = zero;
                }
            }
        }
        cp_commit();
    }
    cp_wait<0>();
    __syncthreads();

    // --- scores (unscaled): warp tile 16q x 80t, k=64 ---
    {
        const int q16   = (wid & 3) * 16;
        const int thalf = (wid >> 2) * 80;
        float acc[10][4];
#pragma unroll
        for (int f = 0; f < 10; f++)
#pragma unroll
            for (int r = 0; r < 4; r++) acc[f][r] = 0.f;
#pragma unroll
        for (int ks = 0; ks < 4; ks++) {
            const int k0 = ks * 16;
            uint32_t a[4];
            ldm_x4(a[0], a[1], a[2], a[3],
                   sb + AQH + (q16 + rowA) * (QP * 2) + (k0 + kA) * 2);
            uint32_t bk[5][4];
#pragma unroll
            for (int np = 0; np < 5; np++)
                ldm_x4(bk[np][0], bk[np][1], bk[np][2], bk[np][3],
                       sb + AKH + (thalf + np * 16 + rowB) * (KP * 2) + (k0 + kB) * 2);
#pragma unroll
            for (int f = 0; f < 10; f++)
                mma16816(acc[f], a, &bk[f >> 1][(f & 1) * 2]);
        }
#pragma unroll
        for (int f = 0; f < 10; f++) {
            const int n = thalf + f * 8 + (lane & 3) * 2;
            const int r = q16 + (lane >> 2);
            *(float2*)&sS[r * SP + n]       = { acc[f][0], acc[f][1] };
            *(float2*)&sS[(r + 8) * SP + n] = { acc[f][2], acc[f][3] };
        }
    }
    __syncthreads();

    // --- overwrite sKh with V via cp.async (overlapped with softmax) ---
    {
        const uint4 zero = {0u, 0u, 0u, 0u};
        for (int i = tid; i < 160 * 8; i += 256) {
            const int r = i >> 3, c = (i & 7) * 8;
            const uint32_t dst = sb + AKH + r * (KP * 2) + c * 2;
            if (r < 128) {
                const int t = qb * MW - MW + r;
                if (t >= 0) cp_async16(dst, qkv + baseV + (size_t)t * C3 + c);
                else        *(uint4*)(smem + AKH + r * (KP * 2) + c * 2) = zero;
            } else {
                const int rr = r - 128, l0 = rr >> 3, ix = rr & 7;
                const int cb = (qb >> l0) - 1;
                if (cb >= 0) {
                    const int nl = 256 >> l0;
                    cp_async16(dst, vpool + POOL_OFF[l0] +
                                    ((size_t)bh * nl + cb * PP + ix) * DH + c);
                } else {
                    *(uint4*)(smem + AKH + r * (KP * 2) + c * 2) = zero;
                }
            }
        }
        cp_commit();
    }

    // --- cross-level softmax (fp32, 1/8 scale folded in) -> fp16 weights ---
    {
        const int qi = tid >> 2, sub = tid & 3;
        float* row = sS + qi * SP;
        __half* wrow = sWh + qi * WP;
        const int lo = qi + 1, hi = qi + 64;
        const int j0 = sub * 32;

        float mx = -1e30f;
#pragma unroll
        for (int j = 0; j < 32; j++) {
            const int t = j0 + j;
            if (t >= lo && t <= hi) mx = fmaxf(mx, row[t] * 0.125f);
        }
        mx = fmaxf(mx, __shfl_xor_sync(0xffffffffu, mx, 1));
        mx = fmaxf(mx, __shfl_xor_sync(0xffffffffu, mx, 2));

        float mc = -1e30f;
#pragma unroll
        for (int i = 0; i < 8; i++) mc = fmaxf(mc, row[128 + sub * 8 + i] * 0.125f);
        float mcm = fminf(mc, __shfl_xor_sync(0xffffffffu, mc, 1));
        mcm = fminf(mcm, __shfl_xor_sync(0xffffffffu, mcm, 2));
        const float mn = fminf(mx, mcm);

        float es = 0.f;
        float ef[32], ec[8];
#pragma unroll
        for (int j = 0; j < 32; j++) {
            const int t = j0 + j;
            float e = 0.f;
            if (t >= lo && t <= hi) { e = __expf(row[t] * 0.125f - mn); es += e; }
            ef[j] = e;
        }
        const float scl = (float)(8 << sub);
#pragma unroll
        for (int i = 0; i < 8; i++) {
            const float e = __expf(row[128 + sub * 8 + i] * 0.125f - mn) * scl;
            ec[i] = e;
            es += e;
        }
        es += __shfl_xor_sync(0xffffffffu, es, 1);
        es += __shfl_xor_sync(0xffffffffu, es, 2);
        const float inv = 1.f / es;
#pragma unroll
        for (int j = 0; j < 32; j++) wrow[j0 + j] = __float2half(ef[j] * inv);
#pragma unroll
        for (int i = 0; i < 8; i++) wrow[128 + sub * 8 + i] = __float2half(ec[i] * inv);
    }
    cp_wait<0>();
    __syncthreads();

    // --- stage 2: O(64x64) = W(64x160) @ V(160x64) ---
    {
        const int q16 = (wid & 3) * 16;
        const int d0  = (wid >> 2) * 32;
        float acc[4][4];
#pragma unroll
        for (int f = 0; f < 4; f++)
#pragma unroll
            for (int r = 0; r < 4; r++) acc[f][r] = 0.f;
#pragma unroll
        for (int ks = 0; ks < 10; ks++) {
            const int t0 = ks * 16;
            uint32_t a[4];
            ldm_x4(a[0], a[1], a[2], a[3],
                   sb + AWH + (q16 + rowA) * (WP * 2) + (t0 + kA) * 2);
            uint32_t bv[2][4];
#pragma unroll
            for (int g = 0; g < 2; g++)
                ldm_x4t(bv[g][0], bv[g][1], bv[g][2], bv[g][3],
                        sb + AKH + (t0 + (lane & 15)) * (KP * 2)
                           + (d0 + g * 16 + ((lane >> 4) << 3)) * 2);
#pragma unroll
            for (int f = 0; f < 4; f++)
                mma16816(acc[f], a, &bv[f >> 1][(f & 1) * 2]);
        }
#pragma unroll
        for (int f = 0; f < 4; f++) {
            const int col = d0 + f * 8 + (lane & 3) * 2;
            const int r0  = q16 + (lane >> 2);
            const int tq0 = qb * MW + r0;
            __half2 v0 = __floats2half2_rn(acc[f][0], acc[f][1]);
            __half2 v1 = __floats2half2_rn(acc[f][2], acc[f][3]);
            *(__half2*)(o + ((size_t)b * T_SZ + tq0) * C_SZ + h * DH + col)     = v0;
            *(__half2*)(o + ((size_t)b * T_SZ + tq0 + 8) * C_SZ + h * DH + col) = v1;
        }
    }
}

// ---------------------------------------------------------------------------
// Launch
// ---------------------------------------------------------------------------
extern "C" void kernel_launch(void* const* d_in, const int* in_sizes, int n_in,
                              void* d_out, int out_size)
{
    (void)in_sizes; (void)n_in; (void)out_size;
    const float* x      = (const float*)d_in[0];
    const float* W_attn = (const float*)d_in[1];
    const float* b_attn = (const float*)d_in[2];
    const float* W_proj = (const float*)d_in[3];
    const float* b_proj = (const float*)d_in[4];
    float* out = (float*)d_out;

    __half *qkvh, *xh, *ah, *kp, *vp, *wta, *wtp;
    cudaGetSymbolAddress((void**)&qkvh, g_qkv_h);
    cudaGetSymbolAddress((void**)&xh,   g_x_h);
    cudaGetSymbolAddress((void**)&ah,   g_attn_h);
    cudaGetSymbolAddress((void**)&kp,   g_kpool);
    cudaGetSymbolAddress((void**)&vp,   g_vpool);
    cudaGetSymbolAddress((void**)&wta,  g_wt_attn);
    cudaGetSymbolAddress((void**)&wtp,  g_wt_proj);

    cudaFuncSetAttribute(mla_attn, cudaFuncAttributeMaxDynamicSharedMemorySize,
                         ATTN2_BYTES);
    cudaFuncSetAttribute(hgemm_bias<0>, cudaFuncAttributeMaxDynamicSharedMemorySize,
                         HGEMM_SMEM);
    cudaFuncSetAttribute(hgemm_bias<1>, cudaFuncAttributeMaxDynamicSharedMemorySize,
                         HGEMM_SMEM);
    cudaFuncSetAttribute(pool_all, cudaFuncAttributeMaxDynamicSharedMemorySize,
                         POOL_SMEM_BYTES);

    // 0) prep
    const size_t nx = (size_t)M_ROWS * C_SZ;
    convert_f2h<<<(unsigned)((nx / 4 + 255) / 256), 256>>>(x, xh, nx);
    transpose_kh<<<dim3(C3 / 32, C_SZ / 32), dim3(32, 8)>>>(W_attn, wta, C_SZ, C3);
    transpose_kh<<<dim3(C_SZ / 32, C_SZ / 32), dim3(32, 8)>>>(W_proj, wtp, C_SZ, C_SZ);

    // 1) qkv = x @ W_attn + b_attn  (fp16 out)
    hgemm_bias<1><<<dim3(C3 / HBN_T, M_ROWS / HBM_T), 256, HGEMM_SMEM>>>(
        xh, wta, b_attn, qkvh, M_ROWS, C3, C_SZ);

    // 2) pooled K/V (fused hierarchical, one kernel)
    pool_all<<<BH, 256, POOL_SMEM_BYTES>>>(qkvh, kp, vp);

    // 3) fused MLA attention (tensor cores) -> fp16
    mla_attn<<<dim3(T_SZ / MW, BH), 256, ATTN2_BYTES>>>(qkvh, kp, vp, ah);

    // 4) out = attn @ W_proj + b_proj  (fp32 out)
    hgemm_bias<0><<<dim3(C_SZ / HBN_T, M_ROWS / HBM_T), 256, HGEMM_SMEM>>>(
        ah, wtp, b_proj, out, M_ROWS, C_SZ, C_SZ);
}

// round 16
// speedup vs baseline: 1.0645x; 1.0645x over previous
#include <cuda_runtime.h>
#include <cuda_fp16.h>
#include <cstdint>

// ---------------------------------------------------------------------------
// Problem constants
// ---------------------------------------------------------------------------
#define B_SZ   8
#define T_SZ   2048
#define C_SZ   1024
#define H_SZ   16
#define DH     64
#define BH     (B_SZ * H_SZ)     // 128
#define C3     (3 * C_SZ)        // 3072
#define M_ROWS (B_SZ * T_SZ)     // 16384
#define MW     64
#define PP     8
#define NLEV   4

__device__ __constant__ size_t POOL_OFF[4] = {
    0,
    (size_t)BH * 256 * DH,
    (size_t)BH * 256 * DH + (size_t)BH * 128 * DH,
    (size_t)BH * 256 * DH + (size_t)BH * 128 * DH + (size_t)BH * 64 * DH
};
#define POOL_TOTAL ((size_t)BH * (256 + 128 + 64 + 32) * DH)

// ---------------------------------------------------------------------------
// Scratch (static device allocations)
// ---------------------------------------------------------------------------
__device__ __half g_qkv_h [(size_t)M_ROWS * C3];     // 100 MB fp16 qkv
__device__ __half g_x_h   [(size_t)M_ROWS * C_SZ];
__device__ __half g_attn_h[(size_t)M_ROWS * C_SZ];
__device__ __half g_kpool [POOL_TOTAL];
__device__ __half g_vpool [POOL_TOTAL];
__device__ __half g_wt_attn[(size_t)C3 * C_SZ];
__device__ __half g_wt_proj[(size_t)C_SZ * C_SZ];

// ===========================================================================
// PTX helpers
// ===========================================================================
__device__ __forceinline__ uint32_t smem_u32(const void* p) {
    uint32_t a;
    asm("{ .reg .u64 t; cvta.to.shared.u64 t, %1; cvt.u32.u64 %0, t; }" : "=r"(a) : "l"(p));
    return a;
}
__device__ __forceinline__ void cp_async16(uint32_t saddr, const void* g) {
    asm volatile("cp.async.cg.shared.global [%0], [%1], 16;" :: "r"(saddr), "l"(g));
}
__device__ __forceinline__ void cp_commit() {
    asm volatile("cp.async.commit_group;" ::: "memory");
}
template <int N>
__device__ __forceinline__ void cp_wait() {
    asm volatile("cp.async.wait_group %0;" :: "n"(N) : "memory");
}
__device__ __forceinline__ void ldm_x4(uint32_t& r0, uint32_t& r1, uint32_t& r2,
                                       uint32_t& r3, uint32_t addr) {
    asm volatile("ldmatrix.sync.aligned.m8n8.x4.shared.b16 {%0,%1,%2,%3}, [%4];"
                 : "=r"(r0), "=r"(r1), "=r"(r2), "=r"(r3) : "r"(addr));
}
__device__ __forceinline__ void ldm_x4t(uint32_t& r0, uint32_t& r1, uint32_t& r2,
                                        uint32_t& r3, uint32_t addr) {
    asm volatile("ldmatrix.sync.aligned.m8n8.x4.trans.shared.b16 {%0,%1,%2,%3}, [%4];"
                 : "=r"(r0), "=r"(r1), "=r"(r2), "=r"(r3) : "r"(addr));
}
__device__ __forceinline__ void mma16816(float* d, const uint32_t* a, const uint32_t* b) {
    asm volatile(
        "mma.sync.aligned.m16n8k16.row.col.f32.f16.f16.f32 "
        "{%0,%1,%2,%3}, {%4,%5,%6,%7}, {%8,%9}, {%0,%1,%2,%3};"
        : "+f"(d[0]), "+f"(d[1]), "+f"(d[2]), "+f"(d[3])
        : "r"(a[0]), "r"(a[1]), "r"(a[2]), "r"(a[3]), "r"(b[0]), "r"(b[1]));
}

// ===========================================================================
// Prep kernels
// ===========================================================================
__global__ void convert_f2h(const float* __restrict__ in, __half* __restrict__ out,
                            size_t n)
{
    const size_t i = ((size_t)blockIdx.x * blockDim.x + threadIdx.x) * 4;
    if (i < n) {
        float4 v = *(const float4*)(in + i);
        *(__half2*)(out + i)     = __floats2half2_rn(v.x, v.y);
        *(__half2*)(out + i + 2) = __floats2half2_rn(v.z, v.w);
    }
}

__global__ void transpose_kh(const float* __restrict__ W, __half* __restrict__ Wt,
                             int K, int N)
{
    __shared__ float t[32][33];
    const int x = blockIdx.x * 32 + threadIdx.x;
    const int y = blockIdx.y * 32 + threadIdx.y;
#pragma unroll
    for (int j = 0; j < 32; j += 8)
        t[threadIdx.y + j][threadIdx.x] = W[(size_t)(y + j) * N + x];
    __syncthreads();
    const int xo = blockIdx.y * 32 + threadIdx.x;
    const int yo = blockIdx.x * 32 + threadIdx.y;
#pragma unroll
    for (int j = 0; j < 32; j += 8)
        Wt[(size_t)(yo + j) * K + xo] = __float2half(t[threadIdx.x][threadIdx.y + j]);
}

// ===========================================================================
// HGEMM: 128x128 tile, K-chunk 64/stage, 3 stages, warp 64x32.
// Verified plateau config (~315-337us, 58% tensor).
// ===========================================================================
#define HBM_T 128
#define HBN_T 128
#define HBK_T 64
#define HSTAGES 3
#define HPITCH 144
#define HSTAGE_BYTES (2 * 128 * HPITCH)                 // 36864
#define HGEMM_SMEM (HSTAGES * HSTAGE_BYTES)             // 110592

template <int HALF_OUT>
__global__ __launch_bounds__(256, 2)
void hgemm_bias(const __half* __restrict__ Ah, const __half* __restrict__ Bh,
                const float* __restrict__ bias, void* __restrict__ Cout,
                int M, int N, int K)
{
    extern __shared__ char smem[];
    const uint32_t sb = smem_u32(smem);
    const int tid  = threadIdx.x;
    const int wid  = tid >> 5;
    const int lane = tid & 31;

    const int row0 = blockIdx.y * HBM_T;
    const int col0 = blockIdx.x * HBN_T;
    const int m0   = (wid & 1) * 64;
    const int n0   = (wid >> 1) * 32;
    const int NT   = K / HBK_T;                          // 16

    const int mat = lane >> 3, li = lane & 7;
    const int rowA = (mat & 1) * 8 + li;
    const int kA   = (mat >> 1) * 8;
    const int rowB = (mat >> 1) * 8 + li;
    const int kB   = (mat & 1) * 8;

    float acc[4][4][4];
#pragma unroll
    for (int i = 0; i < 4; i++)
#pragma unroll
        for (int j = 0; j < 4; j++)
#pragma unroll
            for (int r = 0; r < 4; r++) acc[i][j][r] = 0.f;

    auto load_tile = [&](int t) {
        const uint32_t sA = sb + (t % HSTAGES) * HSTAGE_BYTES;
        const uint32_t sB = sA + 128 * HPITCH;
        const int k0 = t * HBK_T;
#pragma unroll
        for (int i = 0; i < 4; i++) {
            const int id = i * 256 + tid;
            const int r = id >> 3, c = id & 7;
            cp_async16(sA + r * HPITCH + c * 16, Ah + (size_t)(row0 + r) * K + k0 + c * 8);
        }
#pragma unroll
        for (int i = 0; i < 4; i++) {
            const int id = i * 256 + tid;
            const int r = id >> 3, c = id & 7;
            cp_async16(sB + r * HPITCH + c * 16, Bh + (size_t)(col0 + r) * K + k0 + c * 8);
        }
    };

    for (int t = 0; t < HSTAGES - 1; t++) { load_tile(t); cp_commit(); }

    for (int kt = 0; kt < NT; kt++) {
        cp_wait<HSTAGES - 2>();
        __syncthreads();
        const int pf = kt + HSTAGES - 1;
        if (pf < NT) load_tile(pf);
        cp_commit();

        const uint32_t sA = sb + (kt % HSTAGES) * HSTAGE_BYTES;
        const uint32_t sB = sA + 128 * HPITCH;
#pragma unroll
        for (int kc = 0; kc < 4; kc++) {
            uint32_t af[4][4], bf[2][4];
#pragma unroll
            for (int mt = 0; mt < 4; mt++)
                ldm_x4(af[mt][0], af[mt][1], af[mt][2], af[mt][3],
                       sA + (m0 + mt * 16 + rowA) * HPITCH + (kc * 16 + kA) * 2);
#pragma unroll
            for (int np = 0; np < 2; np++)
                ldm_x4(bf[np][0], bf[np][1], bf[np][2], bf[np][3],
                       sB + (n0 + np * 16 + rowB) * HPITCH + (kc * 16 + kB) * 2);
#pragma unroll
            for (int mt = 0; mt < 4; mt++)
#pragma unroll
                for (int nt = 0; nt < 4; nt++)
                    mma16816(acc[mt][nt], af[mt], &bf[nt >> 1][(nt & 1) * 2]);
        }
    }
    cp_wait<0>();

#pragma unroll
    for (int mt = 0; mt < 4; mt++) {
#pragma unroll
        for (int nt = 0; nt < 4; nt++) {
            const int r  = row0 + m0 + mt * 16 + (lane >> 2);
            const int cc = col0 + n0 + nt * 8 + (lane & 3) * 2;
            const float b0 = bias[cc], b1 = bias[cc + 1];
            if (HALF_OUT) {
                __half* C = (__half*)Cout;
                *(__half2*)(C + (size_t)r * N + cc) =
                    __floats2half2_rn(acc[mt][nt][0] + b0, acc[mt][nt][1] + b1);
                *(__half2*)(C + (size_t)(r + 8) * N + cc) =
                    __floats2half2_rn(acc[mt][nt][2] + b0, acc[mt][nt][3] + b1);
            } else {
                float* C = (float*)Cout;
                float2 v0 = { acc[mt][nt][0] + b0, acc[mt][nt][1] + b1 };
                float2 v1 = { acc[mt][nt][2] + b0, acc[mt][nt][3] + b1 };
                *(float2*)(C + (size_t)r * N + cc)       = v0;
                *(float2*)(C + (size_t)(r + 8) * N + cc) = v1;
            }
        }
    }
}

// ---------------------------------------------------------------------------
// Pooling (round-14 verified form: high-parallelism gather + small reduce)
// ---------------------------------------------------------------------------
__global__ void pool0(const __half* __restrict__ qkv,
                      __half* __restrict__ kp, __half* __restrict__ vp)
{
    const int bh = blockIdx.y;
    const int b = bh >> 4, h = bh & 15;
    const size_t kb = (size_t)b * T_SZ * C3 + h * DH + C_SZ;
    const size_t vb = kb + C_SZ;

    for (int idx = threadIdx.x; idx < 32 * 32; idx += 256) {
        const int pi = blockIdx.x * 32 + (idx >> 5);
        const int d2 = (idx & 31) * 2;
        float skx = 0.f, sky = 0.f, svx = 0.f, svy = 0.f;
        const int t0 = pi * 8;
#pragma unroll
        for (int i = 0; i < 8; i++) {
            float2 k2 = __half22float2(*(const __half2*)(qkv + kb + (size_t)(t0 + i) * C3 + d2));
            float2 v2 = __half22float2(*(const __half2*)(qkv + vb + (size_t)(t0 + i) * C3 + d2));
            skx += k2.x; sky += k2.y; svx += v2.x; svy += v2.y;
        }
        const size_t o = ((size_t)bh * 256 + pi) * DH + d2;
        *(__half2*)(kp + o) = __floats2half2_rn(skx * 0.125f, sky * 0.125f);
        *(__half2*)(vp + o) = __floats2half2_rn(svx * 0.125f, svy * 0.125f);
    }
}

__global__ void pool_rest(__half* __restrict__ kp, __half* __restrict__ vp)
{
    const int bh = blockIdx.x;
    for (int l = 1; l <= 3; l++) {
        const int nl = 256 >> l;
        const size_t src = POOL_OFF[l - 1] + (size_t)bh * (nl * 2) * DH;
        const size_t dst = POOL_OFF[l]     + (size_t)bh * nl * DH;
        for (int idx = threadIdx.x; idx < nl * 32; idx += 256) {
            const int pi = idx >> 5, d2 = (idx & 31) * 2;
            {
                float2 a = __half22float2(*(const __half2*)(kp + src + (size_t)(2 * pi) * DH + d2));
                float2 c = __half22float2(*(const __half2*)(kp + src + (size_t)(2 * pi + 1) * DH + d2));
                *(__half2*)(kp + dst + (size_t)pi * DH + d2) =
                    __floats2half2_rn(0.5f * (a.x + c.x), 0.5f * (a.y + c.y));
            }
            {
                float2 a = __half22float2(*(const __half2*)(vp + src + (size_t)(2 * pi) * DH + d2));
                float2 c = __half22float2(*(const __half2*)(vp + src + (size_t)(2 * pi + 1) * DH + d2));
                *(__half2*)(vp + dst + (size_t)pi * DH + d2) =
                    __floats2half2_rn(0.5f * (a.x + c.x), 0.5f * (a.y + c.y));
            }
        }
        __syncthreads();
    }
}

// ---------------------------------------------------------------------------
// Fused MLA attention — tensor cores (round-13/14 verified version).
// Q/K initial loads via cp.async (scale 1/8 folded into softmax);
// V reload via cp.async overlapped with the softmax.
// ---------------------------------------------------------------------------
#define AQH 0
#define AKH 9216
#define ASS 32256
#define AWH 74240
#define ATTN2_BYTES 95744
#define QP  72
#define KP  72
#define SP  164
#define WP  168

__global__ __launch_bounds__(256, 2)
void mla_attn(const __half* __restrict__ qkv,
              const __half* __restrict__ kpool,
              const __half* __restrict__ vpool,
              __half* __restrict__ o)
{
    extern __shared__ char smem[];
    const uint32_t sb = smem_u32(smem);
    float* sS = (float*)(smem + ASS);
    __half* sWh = (__half*)(smem + AWH);

    const int qb  = blockIdx.x;
    const int bh  = blockIdx.y;
    const int b   = bh >> 4, h = bh & 15;
    const int tid = threadIdx.x;
    const int wid = tid >> 5;
    const int lane = tid & 31;

    const size_t baseQ = (size_t)b * T_SZ * C3 + h * DH;
    const size_t baseK = baseQ + C_SZ;
    const size_t baseV = baseQ + 2 * C_SZ;

    const int mat = lane >> 3, li = lane & 7;
    const int rowA = (mat & 1) * 8 + li;
    const int kA   = (mat >> 1) * 8;
    const int rowB = (mat >> 1) * 8 + li;
    const int kB   = (mat & 1) * 8;

    // --- load Q (unscaled) via cp.async ---
    for (int i = tid; i < 64 * 8; i += 256) {
        const int r = i >> 3, c = (i & 7) * 8;
        cp_async16(sb + AQH + r * (QP * 2) + c * 2,
                   qkv + baseQ + (size_t)(qb * MW + r) * C3 + c);
    }
    // --- load K (fine 128 + coarse 32) via cp.async ---
    {
        const uint4 zero = {0u, 0u, 0u, 0u};
        for (int i = tid; i < 160 * 8; i += 256) {
            const int r = i >> 3, c = (i & 7) * 8;
            const uint32_t dst = sb + AKH + r * (KP * 2) + c * 2;
            if (r < 128) {
                const int t = qb * MW - MW + r;
                if (t >= 0) cp_async16(dst, qkv + baseK + (size_t)t * C3 + c);
                else        *(uint4*)(smem + AKH + r * (KP * 2) + c * 2) = zero;
            } else {
                const int rr = r - 128, l0 = rr >> 3, ix = rr & 7;
                const int cb = (qb >> l0) - 1;
                if (cb >= 0) {
                    const int nl = 256 >> l0;
                    cp_async16(dst, kpool + POOL_OFF[l0] +
                                    ((size_t)bh * nl + cb * PP + ix) * DH + c);
                } else {
                    *(uint4*)(smem + AKH + r * (KP * 2) + c * 2) = zero;
                }
            }
        }
        cp_commit();
    }
    cp_wait<0>();
    __syncthreads();

    // --- scores (unscaled): warp tile 16q x 80t, k=64 ---
    {
        const int q16   = (wid & 3) * 16;
        const int thalf = (wid >> 2) * 80;
        float acc[10][4];
#pragma unroll
        for (int f = 0; f < 10; f++)
#pragma unroll
            for (int r = 0; r < 4; r++) acc[f][r] = 0.f;
#pragma unroll
        for (int ks = 0; ks < 4; ks++) {
            const int k0 = ks * 16;
            uint32_t a[4];
            ldm_x4(a[0], a[1], a[2], a[3],
                   sb + AQH + (q16 + rowA) * (QP * 2) + (k0 + kA) * 2);
            uint32_t bk[5][4];
#pragma unroll
            for (int np = 0; np < 5; np++)
                ldm_x4(bk[np][0], bk[np][1], bk[np][2], bk[np][3],
                       sb + AKH + (thalf + np * 16 + rowB) * (KP * 2) + (k0 + kB) * 2);
#pragma unroll
            for (int f = 0; f < 10; f++)
                mma16816(acc[f], a, &bk[f >> 1][(f & 1) * 2]);
        }
#pragma unroll
        for (int f = 0; f < 10; f++) {
            const int n = thalf + f * 8 + (lane & 3) * 2;
            const int r = q16 + (lane >> 2);
            *(float2*)&sS[r * SP + n]       = { acc[f][0], acc[f][1] };
            *(float2*)&sS[(r + 8) * SP + n] = { acc[f][2], acc[f][3] };
        }
    }
    __syncthreads();

    // --- overwrite sKh with V via cp.async (overlapped with softmax) ---
    {
        const uint4 zero = {0u, 0u, 0u, 0u};
        for (int i = tid; i < 160 * 8; i += 256) {
            const int r = i >> 3, c = (i & 7) * 8;
            const uint32_t dst = sb + AKH + r * (KP * 2) + c * 2;
            if (r < 128) {
                const int t = qb * MW - MW + r;
                if (t >= 0) cp_async16(dst, qkv + baseV + (size_t)t * C3 + c);
                else        *(uint4*)(smem + AKH + r * (KP * 2) + c * 2) = zero;
            } else {
                const int rr = r - 128, l0 = rr >> 3, ix = rr & 7;
                const int cb = (qb >> l0) - 1;
                if (cb >= 0) {
                    const int nl = 256 >> l0;
                    cp_async16(dst, vpool + POOL_OFF[l0] +
                                    ((size_t)bh * nl + cb * PP + ix) * DH + c);
                } else {
                    *(uint4*)(smem + AKH + r * (KP * 2) + c * 2) = zero;
                }
            }
        }
        cp_commit();
    }

    // --- cross-level softmax (fp32, 1/8 scale folded in) -> fp16 weights ---
    {
        const int qi = tid >> 2, sub = tid & 3;
        float* row = sS + qi * SP;
        __half* wrow = sWh + qi * WP;
        const int lo = qi + 1, hi = qi + 64;
        const int j0 = sub * 32;

        float mx = -1e30f;
#pragma unroll
        for (int j = 0; j < 32; j++) {
            const int t = j0 + j;
            if (t >= lo && t <= hi) mx = fmaxf(mx, row[t] * 0.125f);
        }
        mx = fmaxf(mx, __shfl_xor_sync(0xffffffffu, mx, 1));
        mx = fmaxf(mx, __shfl_xor_sync(0xffffffffu, mx, 2));

        float mc = -1e30f;
#pragma unroll
        for (int i = 0; i < 8; i++) mc = fmaxf(mc, row[128 + sub * 8 + i] * 0.125f);
        float mcm = fminf(mc, __shfl_xor_sync(0xffffffffu, mc, 1));
        mcm = fminf(mcm, __shfl_xor_sync(0xffffffffu, mcm, 2));
        const float mn = fminf(mx, mcm);

        float es = 0.f;
        float ef[32], ec[8];
#pragma unroll
        for (int j = 0; j < 32; j++) {
            const int t = j0 + j;
            float e = 0.f;
            if (t >= lo && t <= hi) { e = __expf(row[t] * 0.125f - mn); es += e; }
            ef[j] = e;
        }
        const float scl = (float)(8 << sub);
#pragma unroll
        for (int i = 0; i < 8; i++) {
            const float e = __expf(row[128 + sub * 8 + i] * 0.125f - mn) * scl;
            ec[i] = e;
            es += e;
        }
        es += __shfl_xor_sync(0xffffffffu, es, 1);
        es += __shfl_xor_sync(0xffffffffu, es, 2);
        const float inv = 1.f / es;
#pragma unroll
        for (int j = 0; j < 32; j++) wrow[j0 + j] = __float2half(ef[j] * inv);
#pragma unroll
        for (int i = 0; i < 8; i++) wrow[128 + sub * 8 + i] = __float2half(ec[i] * inv);
    }
    cp_wait<0>();
    __syncthreads();

    // --- stage 2: O(64x64) = W(64x160) @ V(160x64) ---
    {
        const int q16 = (wid & 3) * 16;
        const int d0  = (wid >> 2) * 32;
        float acc[4][4];
#pragma unroll
        for (int f = 0; f < 4; f++)
#pragma unroll
            for (int r = 0; r < 4; r++) acc[f][r] = 0.f;
#pragma unroll
        for (int ks = 0; ks < 10; ks++) {
            const int t0 = ks * 16;
            uint32_t a[4];
            ldm_x4(a[0], a[1], a[2], a[3],
                   sb + AWH + (q16 + rowA) * (WP * 2) + (t0 + kA) * 2);
            uint32_t bv[2][4];
#pragma unroll
            for (int g = 0; g < 2; g++)
                ldm_x4t(bv[g][0], bv[g][1], bv[g][2], bv[g][3],
                        sb + AKH + (t0 + (lane & 15)) * (KP * 2)
                           + (d0 + g * 16 + ((lane >> 4) << 3)) * 2);
#pragma unroll
            for (int f = 0; f < 4; f++)
                mma16816(acc[f], a, &bv[f >> 1][(f & 1) * 2]);
        }
#pragma unroll
        for (int f = 0; f < 4; f++) {
            const int col = d0 + f * 8 + (lane & 3) * 2;
            const int r0  = q16 + (lane >> 2);
            const int tq0 = qb * MW + r0;
            __half2 v0 = __floats2half2_rn(acc[f][0], acc[f][1]);
            __half2 v1 = __floats2half2_rn(acc[f][2], acc[f][3]);
            *(__half2*)(o + ((size_t)b * T_SZ + tq0) * C_SZ + h * DH + col)     = v0;
            *(__half2*)(o + ((size_t)b * T_SZ + tq0 + 8) * C_SZ + h * DH + col) = v1;
        }
    }
}

// ---------------------------------------------------------------------------
// Launch
// ---------------------------------------------------------------------------
extern "C" void kernel_launch(void* const* d_in, const int* in_sizes, int n_in,
                              void* d_out, int out_size)
{
    (void)in_sizes; (void)n_in; (void)out_size;
    const float* x      = (const float*)d_in[0];
    const float* W_attn = (const float*)d_in[1];
    const float* b_attn = (const float*)d_in[2];
    const float* W_proj = (const float*)d_in[3];
    const float* b_proj = (const float*)d_in[4];
    float* out = (float*)d_out;

    __half *qkvh, *xh, *ah, *kp, *vp, *wta, *wtp;
    cudaGetSymbolAddress((void**)&qkvh, g_qkv_h);
    cudaGetSymbolAddress((void**)&xh,   g_x_h);
    cudaGetSymbolAddress((void**)&ah,   g_attn_h);
    cudaGetSymbolAddress((void**)&kp,   g_kpool);
    cudaGetSymbolAddress((void**)&vp,   g_vpool);
    cudaGetSymbolAddress((void**)&wta,  g_wt_attn);
    cudaGetSymbolAddress((void**)&wtp,  g_wt_proj);

    cudaFuncSetAttribute(mla_attn, cudaFuncAttributeMaxDynamicSharedMemorySize,
                         ATTN2_BYTES);
    cudaFuncSetAttribute(hgemm_bias<0>, cudaFuncAttributeMaxDynamicSharedMemorySize,
                         HGEMM_SMEM);
    cudaFuncSetAttribute(hgemm_bias<1>, cudaFuncAttributeMaxDynamicSharedMemorySize,
                         HGEMM_SMEM);

    // 0) prep
    const size_t nx = (size_t)M_ROWS * C_SZ;
    convert_f2h<<<(unsigned)((nx / 4 + 255) / 256), 256>>>(x, xh, nx);
    transpose_kh<<<dim3(C3 / 32, C_SZ / 32), dim3(32, 8)>>>(W_attn, wta, C_SZ, C3);
    transpose_kh<<<dim3(C_SZ / 32, C_SZ / 32), dim3(32, 8)>>>(W_proj, wtp, C_SZ, C_SZ);

    // 1) qkv = x @ W_attn + b_attn  (fp16 out)
    hgemm_bias<1><<<dim3(C3 / HBN_T, M_ROWS / HBM_T), 256, HGEMM_SMEM>>>(
        xh, wta, b_attn, qkvh, M_ROWS, C3, C_SZ);

    // 2) pooled K/V (round-14 verified two-kernel form)
    pool0<<<dim3(8, BH), 256>>>(qkvh, kp, vp);
    pool_rest<<<BH, 256>>>(kp, vp);

    // 3) fused MLA attention (tensor cores) -> fp16
    mla_attn<<<dim3(T_SZ / MW, BH), 256, ATTN2_BYTES>>>(qkvh, kp, vp, ah);

    // 4) out = attn @ W_proj + b_proj  (fp32 out)
    hgemm_bias<0><<<dim3(C_SZ / HBN_T, M_ROWS / HBM_T), 256, HGEMM_SMEM>>>(
        ah, wtp, b_proj, out, M_ROWS, C_SZ, C_SZ);
}